// round 13
// baseline (speedup 1.0000x reference)
#include <cuda_runtime.h>
#include <cstdint>

#define N_NODES 25000
#define N_EDGES 400000
#define D       128
#define N_LAYERS 3
#define N_GRAPHS 512
#define D_OUT   10

typedef unsigned int uint;

// ---------------- device scratch ----------------
__device__ float    g_h[N_NODES * D];            // fp32 h3 (pool input)
__device__ unsigned g_hb[N_NODES * D / 2];       // bf16x2 h (gather input)
__device__ unsigned g_whi[N_LAYERS][2][128 * 68]; // bf16x2 W hi, padded pitch 136
__device__ unsigned g_wlo[N_LAYERS][2][128 * 68]; // bf16x2 W lo
__device__ int      g_deg[N_NODES];
__device__ int      g_off[N_NODES + 1];
__device__ int      g_cur[N_NODES];
__device__ int      g_col[N_EDGES];
__device__ int      g_bsum[32];

// ---------------- helpers ----------
__device__ __forceinline__ unsigned bfpack(float e0, float e1) {
    unsigned r;   // low half = bf16(e0), high half = bf16(e1)
    asm("cvt.rn.bf16x2.f32 %0, %1, %2;" : "=r"(r) : "f"(e1), "f"(e0));
    return r;
}
__device__ __forceinline__ float bflo(unsigned p) { return __uint_as_float(p << 16); }
__device__ __forceinline__ float bfhi(unsigned p) { return __uint_as_float(p & 0xFFFF0000u); }

__device__ __forceinline__ uint32_t smem_u32(const void* p) {
    uint32_t a;
    asm("{ .reg .u64 t; cvta.to.shared.u64 t, %1; cvt.u32.u64 %0, t; }" : "=r"(a) : "l"(p));
    return a;
}
__device__ __forceinline__ void cpa16(uint32_t dst, const void* src) {
    asm volatile("cp.async.cg.shared.global [%0], [%1], 16;" :: "r"(dst), "l"(src));
}
#define CPA_COMMIT() asm volatile("cp.async.commit_group;" ::: "memory")
#define CPA_WAIT(n)  asm volatile("cp.async.wait_group %0;" :: "n"(n) : "memory")

__device__ __forceinline__ void ldsm4(uint* r, uint32_t addr) {
    asm volatile("ldmatrix.sync.aligned.m8n8.x4.shared.b16 {%0,%1,%2,%3}, [%4];"
                 : "=r"(r[0]), "=r"(r[1]), "=r"(r[2]), "=r"(r[3]) : "r"(addr));
}
__device__ __forceinline__ void ldsm4t(uint* r, uint32_t addr) {
    asm volatile("ldmatrix.sync.aligned.m8n8.x4.trans.shared.b16 {%0,%1,%2,%3}, [%4];"
                 : "=r"(r[0]), "=r"(r[1]), "=r"(r[2]), "=r"(r[3]) : "r"(addr));
}
__device__ __forceinline__ void mma16816(float* c, const uint* a, const uint* b) {
    asm volatile(
        "mma.sync.aligned.m16n8k16.row.col.f32.bf16.bf16.f32 "
        "{%0,%1,%2,%3}, {%4,%5,%6,%7}, {%8,%9}, {%0,%1,%2,%3};"
        : "+f"(c[0]), "+f"(c[1]), "+f"(c[2]), "+f"(c[3])
        : "r"(a[0]), "r"(a[1]), "r"(a[2]), "r"(a[3]), "r"(b[0]), "r"(b[1]));
}

// ---------------- merged prep: x->bf16, W->hi/lo split, deg=0 ----------------
__global__ void k_prep(const float* __restrict__ x, const float* __restrict__ W1,
                       const float* __restrict__ W2) {
    int t = blockIdx.x * blockDim.x + threadIdx.x;
    if (t < N_NODES * D / 8) {             // 400000: x -> bf16
        float4 v0 = *(const float4*)(x + t * 8);
        float4 v1 = *(const float4*)(x + t * 8 + 4);
        uint4 o;
        o.x = bfpack(v0.x, v0.y);
        o.y = bfpack(v0.z, v0.w);
        o.z = bfpack(v1.x, v1.y);
        o.w = bfpack(v1.z, v1.w);
        *(uint4*)(g_hb + t * 4) = o;
    }
    if (t < 3 * 2 * 128 * 64) {            // 49152: weight hi/lo split
        int e2 = t & 63;
        int r  = (t >> 6) & 127;
        int m  = t >> 13;
        int l = m >> 1, j = m & 1;
        const float* src = (j ? W2 : W1) + (size_t)l * 16384 + r * 128 + e2 * 2;
        float v0 = src[0], v1 = src[1];
        unsigned hi = bfpack(v0, v1);
        unsigned lo = bfpack(v0 - bflo(hi), v1 - bfhi(hi));
        int idx = r * 68 + e2;
        g_whi[l][j][idx] = hi;
        g_wlo[l][j][idx] = lo;
    }
    if (t < N_NODES) g_deg[t] = 0;
}

// ---------------- CSR build ----------------
#define EDGE_Q (N_EDGES / 4)
#define SCAN_BLOCKS 25

__global__ void k_hist(const int* __restrict__ ei) {
    int t = blockIdx.x * blockDim.x + threadIdx.x;
    if (t < EDGE_Q) {
        int d0 = ei[N_EDGES + t];
        int d1 = ei[N_EDGES + t + EDGE_Q];
        int d2 = ei[N_EDGES + t + 2 * EDGE_Q];
        int d3 = ei[N_EDGES + t + 3 * EDGE_Q];
        atomicAdd(&g_deg[d0], 1);
        atomicAdd(&g_deg[d1], 1);
        atomicAdd(&g_deg[d2], 1);
        atomicAdd(&g_deg[d3], 1);
    }
}

// phase A: per-block sum of 1024 degrees -> g_bsum
__global__ void k_scan_a() {
    __shared__ int ws[32];
    int i = blockIdx.x * 1024 + threadIdx.x;
    int v = (i < N_NODES) ? g_deg[i] : 0;
    int lane = threadIdx.x & 31, warp = threadIdx.x >> 5;
    #pragma unroll
    for (int o = 16; o; o >>= 1) v += __shfl_down_sync(0xFFFFFFFFu, v, o);
    if (lane == 0) ws[warp] = v;
    __syncthreads();
    if (warp == 0) {
        int s = ws[lane];
        #pragma unroll
        for (int o = 16; o; o >>= 1) s += __shfl_down_sync(0xFFFFFFFFu, s, o);
        if (lane == 0) g_bsum[blockIdx.x] = s;
    }
}
// phase C: per-block scan + (redundant per-block) scan of block sums
__global__ void k_scan_c() {
    __shared__ int ws[32];
    __shared__ int boff[32];
    int i = blockIdx.x * 1024 + threadIdx.x;
    int v = (i < N_NODES) ? g_deg[i] : 0;
    int lane = threadIdx.x & 31, warp = threadIdx.x >> 5;
    int x = v;
    #pragma unroll
    for (int o = 1; o < 32; o <<= 1) {
        int y = __shfl_up_sync(0xFFFFFFFFu, x, o);
        if (lane >= o) x += y;
    }
    if (lane == 31) ws[warp] = x;
    __syncthreads();
    if (warp == 0) {               // scan warp sums
        int w = ws[lane];
        #pragma unroll
        for (int o = 1; o < 32; o <<= 1) {
            int y = __shfl_up_sync(0xFFFFFFFFu, w, o);
            if (lane >= o) w += y;
        }
        ws[lane] = w;
    } else if (warp == 1) {        // scan block sums (each block redundantly)
        int b = (lane < SCAN_BLOCKS) ? g_bsum[lane] : 0;
        int s = b;
        #pragma unroll
        for (int o = 1; o < 32; o <<= 1) {
            int y = __shfl_up_sync(0xFFFFFFFFu, s, o);
            if (lane >= o) s += y;
        }
        boff[lane] = s - b;        // exclusive
        if (blockIdx.x == 0 && lane == SCAN_BLOCKS - 1) g_off[N_NODES] = s;
    }
    __syncthreads();
    int excl = x - v + ((warp > 0) ? ws[warp - 1] : 0) + boff[blockIdx.x];
    if (i < N_NODES) { g_off[i] = excl; g_cur[i] = excl; }
}

__global__ void k_fill(const int* __restrict__ ei) {
    int t = blockIdx.x * blockDim.x + threadIdx.x;
    if (t < EDGE_Q) {
        #pragma unroll
        for (int i = 0; i < 4; i++) {
            int e = t + i * EDGE_Q;
            int s = ei[e];
            int d = ei[N_EDGES + e];
            int pos = atomicAdd(&g_cur[d], 1);
            g_col[pos] = s;
        }
    }
}

// ---------------- fused layer: gather + GEMM1 + BN + ReLU + GEMM2 ----------
// TILE 192 x 128, 384 threads (12 warps), warp MMA tile 32x64. Grid 131 = 1 wave.
// Gather (GIN agg) done in-kernel from g_hb via CSR, overlapped with weight cp.async.
#define FM 192
#define APITCHB 272                 // bytes per A/W row (136 bf16)
#define OFF_W1H 52224               // 192*272
#define OFF_W1L (OFF_W1H + 34816)   // 128*272
#define OFF_W2H (OFF_W1L + 34816)
#define OFF_W2L (OFF_W2H + 34816)
#define OFF_CONS (OFF_W2L + 34816)  // 191488
#define FUSED_SMEM (OFF_CONS + 1536)

__device__ __forceinline__ void gemm_tile(
    uint32_t aB0, uint32_t aB1, uint32_t wHiB, uint32_t wLoB, float acc[2][8][4])
{
    #pragma unroll
    for (int k0 = 0; k0 < 128; k0 += 16) {
        uint a0[4], a1[4];
        ldsm4(a0, aB0 + k0 * 2);
        ldsm4(a1, aB1 + k0 * 2);
        #pragma unroll
        for (int np = 0; np < 4; np++) {
            uint b[4];
            ldsm4t(b, wHiB + k0 * APITCHB + np * 32);
            mma16816(acc[0][2*np],     a0, b);
            mma16816(acc[0][2*np + 1], a0, b + 2);
            mma16816(acc[1][2*np],     a1, b);
            mma16816(acc[1][2*np + 1], a1, b + 2);
            ldsm4t(b, wLoB + k0 * APITCHB + np * 32);
            mma16816(acc[0][2*np],     a0, b);
            mma16816(acc[0][2*np + 1], a0, b + 2);
            mma16816(acc[1][2*np],     a1, b);
            mma16816(acc[1][2*np + 1], a1, b + 2);
        }
    }
}

template <int LAST>
__global__ void __launch_bounds__(384, 1) k_fused(
    int layer, int M, const float* __restrict__ eps,
    const float* __restrict__ b1, const float* __restrict__ gamma,
    const float* __restrict__ beta, const float* __restrict__ mean,
    const float* __restrict__ var, const float* __restrict__ b2)
{
    extern __shared__ char sm[];
    float* cons = (float*)(sm + OFF_CONS);
    int tid = threadIdx.x;
    int m0 = blockIdx.x * FM;
    uint32_t sb = smem_u32(sm);
    int warp = tid >> 5;
    int lane = tid & 31;

    // ---- weights via cp.async: group0 = W1 hi+lo, group1 = W2 hi+lo ----
    {
        const char* w1h = (const char*)g_whi[layer][0];
        const char* w1l = (const char*)g_wlo[layer][0];
        const char* w2h = (const char*)g_whi[layer][1];
        const char* w2l = (const char*)g_wlo[layer][1];
        for (int i = tid; i < 2176; i += 384) {
            cpa16(sb + OFF_W1H + i * 16, w1h + i * 16);
            cpa16(sb + OFF_W1L + i * 16, w1l + i * 16);
        }
        CPA_COMMIT();
        for (int i = tid; i < 2176; i += 384) {
            cpa16(sb + OFF_W2H + i * 16, w2h + i * 16);
            cpa16(sb + OFF_W2L + i * 16, w2l + i * 16);
        }
        CPA_COMMIT();
        if (tid < 128) {
            float s = gamma[tid] * rsqrtf(var[tid] + 1e-5f);
            cons[tid]       = s;
            cons[128 + tid] = (b1[tid] - mean[tid]) * s + beta[tid];
            cons[256 + tid] = b2[tid];
        }
    }

    // ---- gather (GIN agg) into A tile: warp per node, 16 nodes per warp ----
    {
        float epsv = 1.0f + eps[layer];
        const uint2* hb = (const uint2*)g_hb;
        for (int i = 0; i < 16; i++) {
            int r = warp * 16 + i;
            int node = m0 + r;
            float ax = 0.f, ay = 0.f, az = 0.f, aw = 0.f;
            if (node < M) {
                uint2 sv = hb[(size_t)node * 32 + lane];
                ax = bflo(sv.x) * epsv; ay = bfhi(sv.x) * epsv;
                az = bflo(sv.y) * epsv; aw = bfhi(sv.y) * epsv;
                int e = g_off[node], end = g_off[node + 1];
                for (; e + 7 < end; e += 8) {
                    int c0 = g_col[e],     c1 = g_col[e + 1];
                    int c2 = g_col[e + 2], c3 = g_col[e + 3];
                    int c4 = g_col[e + 4], c5 = g_col[e + 5];
                    int c6 = g_col[e + 6], c7 = g_col[e + 7];
                    uint2 v0 = hb[(size_t)c0 * 32 + lane];
                    uint2 v1 = hb[(size_t)c1 * 32 + lane];
                    uint2 v2 = hb[(size_t)c2 * 32 + lane];
                    uint2 v3 = hb[(size_t)c3 * 32 + lane];
                    uint2 v4 = hb[(size_t)c4 * 32 + lane];
                    uint2 v5 = hb[(size_t)c5 * 32 + lane];
                    uint2 v6 = hb[(size_t)c6 * 32 + lane];
                    uint2 v7 = hb[(size_t)c7 * 32 + lane];
                    ax += ((bflo(v0.x) + bflo(v1.x)) + (bflo(v2.x) + bflo(v3.x)))
                        + ((bflo(v4.x) + bflo(v5.x)) + (bflo(v6.x) + bflo(v7.x)));
                    ay += ((bfhi(v0.x) + bfhi(v1.x)) + (bfhi(v2.x) + bfhi(v3.x)))
                        + ((bfhi(v4.x) + bfhi(v5.x)) + (bfhi(v6.x) + bfhi(v7.x)));
                    az += ((bflo(v0.y) + bflo(v1.y)) + (bflo(v2.y) + bflo(v3.y)))
                        + ((bflo(v4.y) + bflo(v5.y)) + (bflo(v6.y) + bflo(v7.y)));
                    aw += ((bfhi(v0.y) + bfhi(v1.y)) + (bfhi(v2.y) + bfhi(v3.y)))
                        + ((bfhi(v4.y) + bfhi(v5.y)) + (bfhi(v6.y) + bfhi(v7.y)));
                }
                for (; e < end; e++) {
                    int c = g_col[e];
                    uint2 v = hb[(size_t)c * 32 + lane];
                    ax += bflo(v.x); ay += bfhi(v.x);
                    az += bflo(v.y); aw += bfhi(v.y);
                }
            }
            uint2 o;
            o.x = bfpack(ax, ay);
            o.y = bfpack(az, aw);
            *(uint2*)(sm + r * APITCHB + lane * 8) = o;
        }
    }
    CPA_WAIT(1);           // W1 hi/lo landed
    __syncthreads();

    int mBase = (warp % 6) * 32;
    int nBase = (warp / 6) * 64;
    int lr  = lane & 15;
    int lc8 = (lane >> 4) << 3;
    int g = lane >> 2, t = lane & 3;

    uint32_t aB0 = sb + (mBase + lr) * APITCHB + lc8 * 2;
    uint32_t aB1 = aB0 + 16 * APITCHB;
    uint32_t wRow = lr * APITCHB + (nBase + lc8) * 2;

    float acc[2][8][4];
    #pragma unroll
    for (int mt = 0; mt < 2; mt++)
        #pragma unroll
        for (int ng = 0; ng < 8; ng++)
            #pragma unroll
            for (int i = 0; i < 4; i++) acc[mt][ng][i] = 0.f;

    // ---- GEMM1 ----
    gemm_tile(aB0, aB1, sb + OFF_W1H + wRow, sb + OFF_W1L + wRow, acc);

    // ---- BN + ReLU -> z overwrites A ----
    CPA_WAIT(0);           // W2 hi/lo landed
    __syncthreads();       // all A reads complete
    #pragma unroll
    for (int mt = 0; mt < 2; mt++) {
        int r0 = mBase + mt * 16 + g;
        #pragma unroll
        for (int ng = 0; ng < 8; ng++) {
            int colL = nBase + ng * 8 + 2 * t;
            float s0 = cons[colL], s1 = cons[colL + 1];
            float t0 = cons[128 + colL], t1 = cons[128 + colL + 1];
            float z00 = fmaxf(fmaf(acc[mt][ng][0], s0, t0), 0.f);
            float z01 = fmaxf(fmaf(acc[mt][ng][1], s1, t1), 0.f);
            float z10 = fmaxf(fmaf(acc[mt][ng][2], s0, t0), 0.f);
            float z11 = fmaxf(fmaf(acc[mt][ng][3], s1, t1), 0.f);
            *(uint*)(sm + r0 * APITCHB + colL * 2)       = bfpack(z00, z01);
            *(uint*)(sm + (r0 + 8) * APITCHB + colL * 2) = bfpack(z10, z11);
        }
    }
    __syncthreads();

    // ---- GEMM2 ----
    #pragma unroll
    for (int mt = 0; mt < 2; mt++)
        #pragma unroll
        for (int ng = 0; ng < 8; ng++)
            #pragma unroll
            for (int i = 0; i < 4; i++) acc[mt][ng][i] = 0.f;
    gemm_tile(aB0, aB1, sb + OFF_W2H + wRow, sb + OFF_W2L + wRow, acc);

    // ---- bias + ReLU -> output ----
    #pragma unroll
    for (int mt = 0; mt < 2; mt++) {
        int r0 = m0 + mBase + mt * 16 + g;
        #pragma unroll
        for (int ng = 0; ng < 8; ng++) {
            int colL = nBase + ng * 8 + 2 * t;
            float bb0 = cons[256 + colL], bb1 = cons[256 + colL + 1];
            float o00 = fmaxf(acc[mt][ng][0] + bb0, 0.f);
            float o01 = fmaxf(acc[mt][ng][1] + bb1, 0.f);
            float o10 = fmaxf(acc[mt][ng][2] + bb0, 0.f);
            float o11 = fmaxf(acc[mt][ng][3] + bb1, 0.f);
            if (LAST) {
                if (r0 < M)     *(float2*)(g_h + (size_t)r0 * D + colL)       = make_float2(o00, o01);
                if (r0 + 8 < M) *(float2*)(g_h + (size_t)(r0 + 8) * D + colL) = make_float2(o10, o11);
            } else {
                if (r0 < M)     g_hb[(size_t)r0 * 64 + colL / 2]       = bfpack(o00, o01);
                if (r0 + 8 < M) g_hb[(size_t)(r0 + 8) * 64 + colL / 2] = bfpack(o10, o11);
            }
        }
    }
}

// ---------------- mean-pool per graph + final linear ----------------
__global__ void k_pool(const float* __restrict__ h, const int* __restrict__ batch,
                       const float* __restrict__ Wout, const float* __restrict__ bout,
                       float* __restrict__ out)
{
    int g = blockIdx.x;
    int t = threadIdx.x;   // 128

    int lo = 0, hi = N_NODES;
    while (lo < hi) { int mid = (lo + hi) >> 1; if (batch[mid] < g) lo = mid + 1; else hi = mid; }
    int start = lo;
    lo = start; hi = N_NODES;
    while (lo < hi) { int mid = (lo + hi) >> 1; if (batch[mid] < g + 1) lo = mid + 1; else hi = mid; }
    int stop = lo;

    float s = 0.f;
    for (int n = start; n < stop; n++) s += h[(size_t)n * D + t];
    float cnt = fmaxf((float)(stop - start), 1.f);

    __shared__ float sp[D];
    sp[t] = s / cnt;
    __syncthreads();

    if (t < D_OUT) {
        float acc = bout[t];
        #pragma unroll 8
        for (int k = 0; k < D; k++) acc += sp[k] * Wout[k * D_OUT + t];
        out[g * D_OUT + t] = acc;
    }
}

// ---------------- host launcher ----------------
extern "C" void kernel_launch(void* const* d_in, const int* in_sizes, int n_in,
                              void* d_out, int out_size)
{
    const float* x     = (const float*)d_in[0];
    const int*   ei    = (const int*)d_in[1];
    const int*   batch = (const int*)d_in[2];
    const float* W1    = (const float*)d_in[3];
    const float* b1    = (const float*)d_in[4];
    const float* gamma = (const float*)d_in[5];
    const float* beta  = (const float*)d_in[6];
    const float* rmean = (const float*)d_in[7];
    const float* rvar  = (const float*)d_in[8];
    const float* W2    = (const float*)d_in[9];
    const float* b2    = (const float*)d_in[10];
    const float* eps   = (const float*)d_in[11];
    const float* Wout  = (const float*)d_in[12];
    const float* bout  = (const float*)d_in[13];
    float* out = (float*)d_out;

    float* p_h;
    cudaGetSymbolAddress((void**)&p_h, g_h);

    cudaFuncSetAttribute(k_fused<0>, cudaFuncAttributeMaxDynamicSharedMemorySize, FUSED_SMEM);
    cudaFuncSetAttribute(k_fused<1>, cudaFuncAttributeMaxDynamicSharedMemorySize, FUSED_SMEM);

    // ---- prep + CSR build (deterministic every call) ----
    k_prep<<<(N_NODES * D / 8 + 255) / 256, 256>>>(x, W1, W2);
    k_hist<<<(EDGE_Q + 255) / 256, 256>>>(ei);
    k_scan_a<<<SCAN_BLOCKS, 1024>>>();
    k_scan_c<<<SCAN_BLOCKS, 1024>>>();
    k_fill<<<(EDGE_Q + 255) / 256, 256>>>(ei);

    const int fused_blocks = (N_NODES + FM - 1) / FM;    // 131

    for (int l = 0; l < N_LAYERS; l++) {
        if (l < N_LAYERS - 1) {
            k_fused<0><<<fused_blocks, 384, FUSED_SMEM>>>(
                l, N_NODES, eps, b1 + l * D, gamma + l * D, beta + l * D,
                rmean + l * D, rvar + l * D, b2 + l * D);
        } else {
            k_fused<1><<<fused_blocks, 384, FUSED_SMEM>>>(
                l, N_NODES, eps, b1 + l * D, gamma + l * D, beta + l * D,
                rmean + l * D, rvar + l * D, b2 + l * D);
        }
    }

    k_pool<<<N_GRAPHS, D>>>(p_h, batch, Wout, bout, out);
}

// round 14
// speedup vs baseline: 1.3955x; 1.3955x over previous
#include <cuda_runtime.h>
#include <cstdint>

#define N_NODES 25000
#define N_EDGES 400000
#define D       128
#define N_LAYERS 3
#define N_GRAPHS 512
#define D_OUT   10

typedef unsigned int uint;

// ---------------- device scratch ----------------
__device__ float    g_h[N_NODES * D];            // fp32 h3 (pool input)
__device__ unsigned g_hb[N_NODES * D / 2];       // bf16x2 h (agg input)
__device__ unsigned g_aggb[N_NODES * D / 2];     // bf16x2 agg (GEMM1 A input)
__device__ unsigned g_whi[N_LAYERS][2][128 * 68]; // bf16x2 W hi, padded pitch 136
__device__ unsigned g_wlo[N_LAYERS][2][128 * 68]; // bf16x2 W lo
__device__ int      g_deg[N_NODES];
__device__ int      g_off[N_NODES + 1];
__device__ int      g_cur[N_NODES];
__device__ int      g_col[N_EDGES];
__device__ int      g_bsum[32];

// ---------------- helpers ----------
__device__ __forceinline__ unsigned bfpack(float e0, float e1) {
    unsigned r;   // low half = bf16(e0), high half = bf16(e1)
    asm("cvt.rn.bf16x2.f32 %0, %1, %2;" : "=r"(r) : "f"(e1), "f"(e0));
    return r;
}
__device__ __forceinline__ float bflo(unsigned p) { return __uint_as_float(p << 16); }
__device__ __forceinline__ float bfhi(unsigned p) { return __uint_as_float(p & 0xFFFF0000u); }

__device__ __forceinline__ uint32_t smem_u32(const void* p) {
    uint32_t a;
    asm("{ .reg .u64 t; cvta.to.shared.u64 t, %1; cvt.u32.u64 %0, t; }" : "=r"(a) : "l"(p));
    return a;
}
__device__ __forceinline__ void cpa16(uint32_t dst, const void* src) {
    asm volatile("cp.async.cg.shared.global [%0], [%1], 16;" :: "r"(dst), "l"(src));
}
#define CPA_COMMIT() asm volatile("cp.async.commit_group;" ::: "memory")
#define CPA_WAIT(n)  asm volatile("cp.async.wait_group %0;" :: "n"(n) : "memory")

__device__ __forceinline__ void ldsm4(uint* r, uint32_t addr) {
    asm volatile("ldmatrix.sync.aligned.m8n8.x4.shared.b16 {%0,%1,%2,%3}, [%4];"
                 : "=r"(r[0]), "=r"(r[1]), "=r"(r[2]), "=r"(r[3]) : "r"(addr));
}
__device__ __forceinline__ void ldsm4t(uint* r, uint32_t addr) {
    asm volatile("ldmatrix.sync.aligned.m8n8.x4.trans.shared.b16 {%0,%1,%2,%3}, [%4];"
                 : "=r"(r[0]), "=r"(r[1]), "=r"(r[2]), "=r"(r[3]) : "r"(addr));
}
__device__ __forceinline__ void mma16816(float* c, const uint* a, const uint* b) {
    asm volatile(
        "mma.sync.aligned.m16n8k16.row.col.f32.bf16.bf16.f32 "
        "{%0,%1,%2,%3}, {%4,%5,%6,%7}, {%8,%9}, {%0,%1,%2,%3};"
        : "+f"(c[0]), "+f"(c[1]), "+f"(c[2]), "+f"(c[3])
        : "r"(a[0]), "r"(a[1]), "r"(a[2]), "r"(a[3]), "r"(b[0]), "r"(b[1]));
}

// ---------------- merged prep: x->bf16, W->hi/lo split, deg=0 ----------------
__global__ void k_prep(const float* __restrict__ x, const float* __restrict__ W1,
                       const float* __restrict__ W2) {
    int t = blockIdx.x * blockDim.x + threadIdx.x;
    if (t < N_NODES * D / 8) {             // 400000: x -> bf16
        float4 v0 = *(const float4*)(x + t * 8);
        float4 v1 = *(const float4*)(x + t * 8 + 4);
        uint4 o;
        o.x = bfpack(v0.x, v0.y);
        o.y = bfpack(v0.z, v0.w);
        o.z = bfpack(v1.x, v1.y);
        o.w = bfpack(v1.z, v1.w);
        *(uint4*)(g_hb + t * 4) = o;
    }
    if (t < 3 * 2 * 128 * 64) {            // 49152: weight hi/lo split
        int e2 = t & 63;
        int r  = (t >> 6) & 127;
        int m  = t >> 13;
        int l = m >> 1, j = m & 1;
        const float* src = (j ? W2 : W1) + (size_t)l * 16384 + r * 128 + e2 * 2;
        float v0 = src[0], v1 = src[1];
        unsigned hi = bfpack(v0, v1);
        unsigned lo = bfpack(v0 - bflo(hi), v1 - bfhi(hi));
        int idx = r * 68 + e2;
        g_whi[l][j][idx] = hi;
        g_wlo[l][j][idx] = lo;
    }
    if (t < N_NODES) g_deg[t] = 0;
}

// ---------------- CSR build ----------------
#define EDGE_Q (N_EDGES / 4)
#define SCAN_BLOCKS 25

__global__ void k_hist(const int* __restrict__ ei) {
    int t = blockIdx.x * blockDim.x + threadIdx.x;
    if (t < EDGE_Q) {
        int d0 = ei[N_EDGES + t];
        int d1 = ei[N_EDGES + t + EDGE_Q];
        int d2 = ei[N_EDGES + t + 2 * EDGE_Q];
        int d3 = ei[N_EDGES + t + 3 * EDGE_Q];
        atomicAdd(&g_deg[d0], 1);
        atomicAdd(&g_deg[d1], 1);
        atomicAdd(&g_deg[d2], 1);
        atomicAdd(&g_deg[d3], 1);
    }
}

// phase A: per-block sum of 1024 degrees -> g_bsum
__global__ void k_scan_a() {
    __shared__ int ws[32];
    int i = blockIdx.x * 1024 + threadIdx.x;
    int v = (i < N_NODES) ? g_deg[i] : 0;
    int lane = threadIdx.x & 31, warp = threadIdx.x >> 5;
    #pragma unroll
    for (int o = 16; o; o >>= 1) v += __shfl_down_sync(0xFFFFFFFFu, v, o);
    if (lane == 0) ws[warp] = v;
    __syncthreads();
    if (warp == 0) {
        int s = ws[lane];
        #pragma unroll
        for (int o = 16; o; o >>= 1) s += __shfl_down_sync(0xFFFFFFFFu, s, o);
        if (lane == 0) g_bsum[blockIdx.x] = s;
    }
}
// phase C: per-block scan + (redundant per-block) scan of block sums
__global__ void k_scan_c() {
    __shared__ int ws[32];
    __shared__ int boff[32];
    int i = blockIdx.x * 1024 + threadIdx.x;
    int v = (i < N_NODES) ? g_deg[i] : 0;
    int lane = threadIdx.x & 31, warp = threadIdx.x >> 5;
    int x = v;
    #pragma unroll
    for (int o = 1; o < 32; o <<= 1) {
        int y = __shfl_up_sync(0xFFFFFFFFu, x, o);
        if (lane >= o) x += y;
    }
    if (lane == 31) ws[warp] = x;
    __syncthreads();
    if (warp == 0) {               // scan warp sums
        int w = ws[lane];
        #pragma unroll
        for (int o = 1; o < 32; o <<= 1) {
            int y = __shfl_up_sync(0xFFFFFFFFu, w, o);
            if (lane >= o) w += y;
        }
        ws[lane] = w;
    } else if (warp == 1) {        // scan block sums (each block redundantly)
        int b = (lane < SCAN_BLOCKS) ? g_bsum[lane] : 0;
        int s = b;
        #pragma unroll
        for (int o = 1; o < 32; o <<= 1) {
            int y = __shfl_up_sync(0xFFFFFFFFu, s, o);
            if (lane >= o) s += y;
        }
        boff[lane] = s - b;        // exclusive
        if (blockIdx.x == 0 && lane == SCAN_BLOCKS - 1) g_off[N_NODES] = s;
    }
    __syncthreads();
    int excl = x - v + ((warp > 0) ? ws[warp - 1] : 0) + boff[blockIdx.x];
    if (i < N_NODES) { g_off[i] = excl; g_cur[i] = excl; }
}

__global__ void k_fill(const int* __restrict__ ei) {
    int t = blockIdx.x * blockDim.x + threadIdx.x;
    if (t < EDGE_Q) {
        #pragma unroll
        for (int i = 0; i < 4; i++) {
            int e = t + i * EDGE_Q;
            int s = ei[e];
            int d = ei[N_EDGES + e];
            int pos = atomicAdd(&g_cur[d], 1);
            g_col[pos] = s;
        }
    }
}

// ---------------- GIN aggregation (bf16 in, fp32 acc, bf16 out) ----------
__global__ void k_agg(const float* __restrict__ eps, int layer) {
    int gt = blockIdx.x * blockDim.x + threadIdx.x;
    int node = gt >> 5;
    if (node >= N_NODES) return;
    int lane = gt & 31;
    float epsv = 1.0f + eps[layer];
    const uint2* hb = (const uint2*)g_hb;
    uint2 sv = hb[(size_t)node * 32 + lane];
    float4 acc;
    acc.x = bflo(sv.x) * epsv; acc.y = bfhi(sv.x) * epsv;
    acc.z = bflo(sv.y) * epsv; acc.w = bfhi(sv.y) * epsv;
    int e = g_off[node], end = g_off[node + 1];
    for (; e + 3 < end; e += 4) {
        int c0 = g_col[e], c1 = g_col[e + 1], c2 = g_col[e + 2], c3 = g_col[e + 3];
        uint2 v0 = hb[(size_t)c0 * 32 + lane];
        uint2 v1 = hb[(size_t)c1 * 32 + lane];
        uint2 v2 = hb[(size_t)c2 * 32 + lane];
        uint2 v3 = hb[(size_t)c3 * 32 + lane];
        acc.x += (bflo(v0.x) + bflo(v1.x)) + (bflo(v2.x) + bflo(v3.x));
        acc.y += (bfhi(v0.x) + bfhi(v1.x)) + (bfhi(v2.x) + bfhi(v3.x));
        acc.z += (bflo(v0.y) + bflo(v1.y)) + (bflo(v2.y) + bflo(v3.y));
        acc.w += (bfhi(v0.y) + bfhi(v1.y)) + (bfhi(v2.y) + bfhi(v3.y));
    }
    for (; e < end; e++) {
        int c = g_col[e];
        uint2 v = hb[(size_t)c * 32 + lane];
        acc.x += bflo(v.x); acc.y += bfhi(v.x);
        acc.z += bflo(v.y); acc.w += bfhi(v.y);
    }
    uint2 o;
    o.x = bfpack(acc.x, acc.y);
    o.y = bfpack(acc.z, acc.w);
    ((uint2*)g_aggb)[(size_t)node * 32 + lane] = o;
}

// ---------------- fused layer via mma.sync (HMMA bf16, f32 acc) ----------
// TILE 192 x 128, 384 threads (12 warps), warp tile 32x64. Grid 131 = 1 wave.
#define FM 192
#define APITCHB 272                 // bytes per A/W row (136 bf16)
#define OFF_W1H 52224               // 192*272
#define OFF_W1L (OFF_W1H + 34816)   // 128*272
#define OFF_W2H (OFF_W1L + 34816)
#define OFF_W2L (OFF_W2H + 34816)
#define OFF_CONS (OFF_W2L + 34816)  // 191488
#define FUSED_SMEM (OFF_CONS + 1536)

__device__ __forceinline__ void gemm_tile(
    uint32_t aB0, uint32_t aB1, uint32_t wHiB, uint32_t wLoB, float acc[2][8][4])
{
    #pragma unroll
    for (int k0 = 0; k0 < 128; k0 += 16) {
        uint a0[4], a1[4];
        ldsm4(a0, aB0 + k0 * 2);
        ldsm4(a1, aB1 + k0 * 2);
        #pragma unroll
        for (int np = 0; np < 4; np++) {
            uint b[4];
            ldsm4t(b, wHiB + k0 * APITCHB + np * 32);
            mma16816(acc[0][2*np],     a0, b);
            mma16816(acc[0][2*np + 1], a0, b + 2);
            mma16816(acc[1][2*np],     a1, b);
            mma16816(acc[1][2*np + 1], a1, b + 2);
            ldsm4t(b, wLoB + k0 * APITCHB + np * 32);
            mma16816(acc[0][2*np],     a0, b);
            mma16816(acc[0][2*np + 1], a0, b + 2);
            mma16816(acc[1][2*np],     a1, b);
            mma16816(acc[1][2*np + 1], a1, b + 2);
        }
    }
}

template <int LAST>
__global__ void __launch_bounds__(384, 1) k_fused(
    int layer, int M,
    const float* __restrict__ b1, const float* __restrict__ gamma,
    const float* __restrict__ beta, const float* __restrict__ mean,
    const float* __restrict__ var, const float* __restrict__ b2)
{
    extern __shared__ char sm[];
    float* cons = (float*)(sm + OFF_CONS);
    int tid = threadIdx.x;
    int m0 = blockIdx.x * FM;
    uint32_t sb = smem_u32(sm);

    // ---- weights via cp.async: group0 = W1 hi+lo, group1 = W2 hi+lo ----
    {
        const char* w1h = (const char*)g_whi[layer][0];
        const char* w1l = (const char*)g_wlo[layer][0];
        const char* w2h = (const char*)g_whi[layer][1];
        const char* w2l = (const char*)g_wlo[layer][1];
        for (int i = tid; i < 2176; i += 384) {
            cpa16(sb + OFF_W1H + i * 16, w1h + i * 16);
            cpa16(sb + OFF_W1L + i * 16, w1l + i * 16);
        }
        CPA_COMMIT();
        for (int i = tid; i < 2176; i += 384) {
            cpa16(sb + OFF_W2H + i * 16, w2h + i * 16);
            cpa16(sb + OFF_W2L + i * 16, w2l + i * 16);
        }
        CPA_COMMIT();
    }
    // ---- A tile: bf16 from g_aggb, 16B chunks, padded pitch ----
    {
        #pragma unroll
        for (int i = 0; i < 8; i++) {
            int idx = tid + i * 384;          // 0..3071
            int r = idx >> 4, c16 = idx & 15;
            int row = m0 + r;
            uint4 v = (row < M) ? *(const uint4*)(g_aggb + (size_t)row * 64 + c16 * 4)
                                : make_uint4(0, 0, 0, 0);
            *(uint4*)(sm + r * APITCHB + c16 * 16) = v;
        }
        if (tid < 128) {
            float s = gamma[tid] * rsqrtf(var[tid] + 1e-5f);
            cons[tid]       = s;
            cons[128 + tid] = (b1[tid] - mean[tid]) * s + beta[tid];
            cons[256 + tid] = b2[tid];
        }
    }
    CPA_WAIT(1);           // W1 hi/lo landed
    __syncthreads();

    int warp = tid >> 5;
    int lane = tid & 31;
    int mBase = (warp % 6) * 32;
    int nBase = (warp / 6) * 64;
    int lr  = lane & 15;
    int lc8 = (lane >> 4) << 3;
    int g = lane >> 2, t = lane & 3;

    uint32_t aB0 = sb + (mBase + lr) * APITCHB + lc8 * 2;
    uint32_t aB1 = aB0 + 16 * APITCHB;
    uint32_t wRow = lr * APITCHB + (nBase + lc8) * 2;

    float acc[2][8][4];
    #pragma unroll
    for (int mt = 0; mt < 2; mt++)
        #pragma unroll
        for (int ng = 0; ng < 8; ng++)
            #pragma unroll
            for (int i = 0; i < 4; i++) acc[mt][ng][i] = 0.f;

    // ---- GEMM1 ----
    gemm_tile(aB0, aB1, sb + OFF_W1H + wRow, sb + OFF_W1L + wRow, acc);

    // ---- BN + ReLU -> z overwrites A ----
    CPA_WAIT(0);           // W2 hi/lo landed
    __syncthreads();       // all A reads complete
    #pragma unroll
    for (int mt = 0; mt < 2; mt++) {
        int r0 = mBase + mt * 16 + g;
        #pragma unroll
        for (int ng = 0; ng < 8; ng++) {
            int colL = nBase + ng * 8 + 2 * t;
            float s0 = cons[colL], s1 = cons[colL + 1];
            float t0 = cons[128 + colL], t1 = cons[128 + colL + 1];
            float z00 = fmaxf(fmaf(acc[mt][ng][0], s0, t0), 0.f);
            float z01 = fmaxf(fmaf(acc[mt][ng][1], s1, t1), 0.f);
            float z10 = fmaxf(fmaf(acc[mt][ng][2], s0, t0), 0.f);
            float z11 = fmaxf(fmaf(acc[mt][ng][3], s1, t1), 0.f);
            *(uint*)(sm + r0 * APITCHB + colL * 2)       = bfpack(z00, z01);
            *(uint*)(sm + (r0 + 8) * APITCHB + colL * 2) = bfpack(z10, z11);
        }
    }
    __syncthreads();

    // ---- GEMM2 ----
    #pragma unroll
    for (int mt = 0; mt < 2; mt++)
        #pragma unroll
        for (int ng = 0; ng < 8; ng++)
            #pragma unroll
            for (int i = 0; i < 4; i++) acc[mt][ng][i] = 0.f;
    gemm_tile(aB0, aB1, sb + OFF_W2H + wRow, sb + OFF_W2L + wRow, acc);

    // ---- bias + ReLU -> output ----
    #pragma unroll
    for (int mt = 0; mt < 2; mt++) {
        int r0 = m0 + mBase + mt * 16 + g;
        #pragma unroll
        for (int ng = 0; ng < 8; ng++) {
            int colL = nBase + ng * 8 + 2 * t;
            float bb0 = cons[256 + colL], bb1 = cons[256 + colL + 1];
            float o00 = fmaxf(acc[mt][ng][0] + bb0, 0.f);
            float o01 = fmaxf(acc[mt][ng][1] + bb1, 0.f);
            float o10 = fmaxf(acc[mt][ng][2] + bb0, 0.f);
            float o11 = fmaxf(acc[mt][ng][3] + bb1, 0.f);
            if (LAST) {
                if (r0 < M)     *(float2*)(g_h + (size_t)r0 * D + colL)       = make_float2(o00, o01);
                if (r0 + 8 < M) *(float2*)(g_h + (size_t)(r0 + 8) * D + colL) = make_float2(o10, o11);
            } else {
                if (r0 < M)     g_hb[(size_t)r0 * 64 + colL / 2]       = bfpack(o00, o01);
                if (r0 + 8 < M) g_hb[(size_t)(r0 + 8) * 64 + colL / 2] = bfpack(o10, o11);
            }
        }
    }
}

// ---------------- mean-pool per graph + final linear ----------------
__global__ void k_pool(const float* __restrict__ h, const int* __restrict__ batch,
                       const float* __restrict__ Wout, const float* __restrict__ bout,
                       float* __restrict__ out)
{
    int g = blockIdx.x;
    int t = threadIdx.x;   // 128

    int lo = 0, hi = N_NODES;
    while (lo < hi) { int mid = (lo + hi) >> 1; if (batch[mid] < g) lo = mid + 1; else hi = mid; }
    int start = lo;
    lo = start; hi = N_NODES;
    while (lo < hi) { int mid = (lo + hi) >> 1; if (batch[mid] < g + 1) lo = mid + 1; else hi = mid; }
    int stop = lo;

    float s = 0.f;
    for (int n = start; n < stop; n++) s += h[(size_t)n * D + t];
    float cnt = fmaxf((float)(stop - start), 1.f);

    __shared__ float sp[D];
    sp[t] = s / cnt;
    __syncthreads();

    if (t < D_OUT) {
        float acc = bout[t];
        #pragma unroll 8
        for (int k = 0; k < D; k++) acc += sp[k] * Wout[k * D_OUT + t];
        out[g * D_OUT + t] = acc;
    }
}

// ---------------- host launcher ----------------
extern "C" void kernel_launch(void* const* d_in, const int* in_sizes, int n_in,
                              void* d_out, int out_size)
{
    const float* x     = (const float*)d_in[0];
    const int*   ei    = (const int*)d_in[1];
    const int*   batch = (const int*)d_in[2];
    const float* W1    = (const float*)d_in[3];
    const float* b1    = (const float*)d_in[4];
    const float* gamma = (const float*)d_in[5];
    const float* beta  = (const float*)d_in[6];
    const float* rmean = (const float*)d_in[7];
    const float* rvar  = (const float*)d_in[8];
    const float* W2    = (const float*)d_in[9];
    const float* b2    = (const float*)d_in[10];
    const float* eps   = (const float*)d_in[11];
    const float* Wout  = (const float*)d_in[12];
    const float* bout  = (const float*)d_in[13];
    float* out = (float*)d_out;

    float* p_h;
    cudaGetSymbolAddress((void**)&p_h, g_h);

    cudaFuncSetAttribute(k_fused<0>, cudaFuncAttributeMaxDynamicSharedMemorySize, FUSED_SMEM);
    cudaFuncSetAttribute(k_fused<1>, cudaFuncAttributeMaxDynamicSharedMemorySize, FUSED_SMEM);

    // ---- prep + CSR build (deterministic every call) ----
    k_prep<<<(N_NODES * D / 8 + 255) / 256, 256>>>(x, W1, W2);
    k_hist<<<(EDGE_Q + 255) / 256, 256>>>(ei);
    k_scan_a<<<SCAN_BLOCKS, 1024>>>();
    k_scan_c<<<SCAN_BLOCKS, 1024>>>();
    k_fill<<<(EDGE_Q + 255) / 256, 256>>>(ei);

    const int fused_blocks = (N_NODES + FM - 1) / FM;    // 131
    const int agg_blocks   = (N_NODES * 32 + 255) / 256;

    for (int l = 0; l < N_LAYERS; l++) {
        k_agg<<<agg_blocks, 256>>>(eps, l);
        if (l < N_LAYERS - 1) {
            k_fused<0><<<fused_blocks, 384, FUSED_SMEM>>>(
                l, N_NODES, b1 + l * D, gamma + l * D, beta + l * D,
                rmean + l * D, rvar + l * D, b2 + l * D);
        } else {
            k_fused<1><<<fused_blocks, 384, FUSED_SMEM>>>(
                l, N_NODES, b1 + l * D, gamma + l * D, beta + l * D,
                rmean + l * D, rvar + l * D, b2 + l * D);
        }
    }

    k_pool<<<N_GRAPHS, D>>>(p_h, batch, Wout, bout, out);
}

// round 15
// speedup vs baseline: 1.4278x; 1.0232x over previous
#include <cuda_runtime.h>
#include <cstdint>

#define N_NODES 25000
#define N_EDGES 400000
#define D       128
#define N_LAYERS 3
#define N_GRAPHS 512
#define D_OUT   10

typedef unsigned int uint;

// ---------------- device scratch ----------------
// NOTE: g_deg and g_bsum are zero at module load AND re-zeroed by k_pool at
// the END of every launch, so every kernel_launch execution (correctness run,
// capture replays) starts from the same zeroed state. Deterministic.
__device__ float    g_h[N_NODES * D];            // fp32 h3 (pool input)
__device__ unsigned g_hb[N_NODES * D / 2];       // bf16x2 h (agg input)
__device__ unsigned g_aggb[N_NODES * D / 2];     // bf16x2 agg (GEMM1 A input)
__device__ unsigned g_whi[N_LAYERS][2][128 * 68]; // bf16x2 W hi, padded pitch 136
__device__ unsigned g_wlo[N_LAYERS][2][128 * 68]; // bf16x2 W lo
__device__ int      g_deg[N_NODES];
__device__ int      g_off[N_NODES + 1];
__device__ int      g_cur[N_NODES];
__device__ int      g_col[N_EDGES];
__device__ int      g_bsum[32];

// ---------------- helpers ----------
__device__ __forceinline__ unsigned bfpack(float e0, float e1) {
    unsigned r;   // low half = bf16(e0), high half = bf16(e1)
    asm("cvt.rn.bf16x2.f32 %0, %1, %2;" : "=r"(r) : "f"(e1), "f"(e0));
    return r;
}
__device__ __forceinline__ float bflo(unsigned p) { return __uint_as_float(p << 16); }
__device__ __forceinline__ float bfhi(unsigned p) { return __uint_as_float(p & 0xFFFF0000u); }

__device__ __forceinline__ uint32_t smem_u32(const void* p) {
    uint32_t a;
    asm("{ .reg .u64 t; cvta.to.shared.u64 t, %1; cvt.u32.u64 %0, t; }" : "=r"(a) : "l"(p));
    return a;
}
__device__ __forceinline__ void cpa16(uint32_t dst, const void* src) {
    asm volatile("cp.async.cg.shared.global [%0], [%1], 16;" :: "r"(dst), "l"(src));
}
#define CPA_COMMIT() asm volatile("cp.async.commit_group;" ::: "memory")
#define CPA_WAIT(n)  asm volatile("cp.async.wait_group %0;" :: "n"(n) : "memory")

__device__ __forceinline__ void ldsm4(uint* r, uint32_t addr) {
    asm volatile("ldmatrix.sync.aligned.m8n8.x4.shared.b16 {%0,%1,%2,%3}, [%4];"
                 : "=r"(r[0]), "=r"(r[1]), "=r"(r[2]), "=r"(r[3]) : "r"(addr));
}
__device__ __forceinline__ void ldsm4t(uint* r, uint32_t addr) {
    asm volatile("ldmatrix.sync.aligned.m8n8.x4.trans.shared.b16 {%0,%1,%2,%3}, [%4];"
                 : "=r"(r[0]), "=r"(r[1]), "=r"(r[2]), "=r"(r[3]) : "r"(addr));
}
__device__ __forceinline__ void mma16816(float* c, const uint* a, const uint* b) {
    asm volatile(
        "mma.sync.aligned.m16n8k16.row.col.f32.bf16.bf16.f32 "
        "{%0,%1,%2,%3}, {%4,%5,%6,%7}, {%8,%9}, {%0,%1,%2,%3};"
        : "+f"(c[0]), "+f"(c[1]), "+f"(c[2]), "+f"(c[3])
        : "r"(a[0]), "r"(a[1]), "r"(a[2]), "r"(a[3]), "r"(b[0]), "r"(b[1]));
}

// ---------------- prep: x->bf16, W->hi/lo split, degree histogram ----------
// g_deg is guaranteed zero at launch start (zeroed by k_pool last launch /
// module load), so the histogram can run in the same kernel as the converts.
#define EDGE_Q (N_EDGES / 4)

__global__ void k_prep(const float* __restrict__ x, const float* __restrict__ W1,
                       const float* __restrict__ W2, const int* __restrict__ ei) {
    int t = blockIdx.x * blockDim.x + threadIdx.x;
    if (t < N_NODES * D / 8) {             // 400000: x -> bf16
        float4 v0 = *(const float4*)(x + t * 8);
        float4 v1 = *(const float4*)(x + t * 8 + 4);
        uint4 o;
        o.x = bfpack(v0.x, v0.y);
        o.y = bfpack(v0.z, v0.w);
        o.z = bfpack(v1.x, v1.y);
        o.w = bfpack(v1.z, v1.w);
        *(uint4*)(g_hb + t * 4) = o;
    }
    if (t < 3 * 2 * 128 * 64) {            // 49152: weight hi/lo split
        int e2 = t & 63;
        int r  = (t >> 6) & 127;
        int m  = t >> 13;
        int l = m >> 1, j = m & 1;
        const float* src = (j ? W2 : W1) + (size_t)l * 16384 + r * 128 + e2 * 2;
        float v0 = src[0], v1 = src[1];
        unsigned hi = bfpack(v0, v1);
        unsigned lo = bfpack(v0 - bflo(hi), v1 - bfhi(hi));
        int idx = r * 68 + e2;
        g_whi[l][j][idx] = hi;
        g_wlo[l][j][idx] = lo;
    }
    if (t < EDGE_Q) {                      // 100000: degree histogram (4 edges)
        int d0 = ei[N_EDGES + t];
        int d1 = ei[N_EDGES + t + EDGE_Q];
        int d2 = ei[N_EDGES + t + 2 * EDGE_Q];
        int d3 = ei[N_EDGES + t + 3 * EDGE_Q];
        atomicAdd(&g_deg[d0], 1);
        atomicAdd(&g_deg[d1], 1);
        atomicAdd(&g_deg[d2], 1);
        atomicAdd(&g_deg[d3], 1);
    }
}

// ---------------- single-kernel scan with inter-block spin lookback --------
// 25 blocks (all resident: 25 < 148 SMs -> no deadlock). Each block publishes
// blockSum+1 into g_bsum[bid] (fence+atomicExch), warp 1 spins on all 25
// flags and exclusive-scans them. g_bsum is zero at launch start.
#define SCAN_BLOCKS 25

__global__ void k_scan() {
    __shared__ int ws[32];
    __shared__ int boff[32];
    int bid = blockIdx.x;
    int i = bid * 1024 + threadIdx.x;
    int v = (i < N_NODES) ? g_deg[i] : 0;
    int lane = threadIdx.x & 31, warp = threadIdx.x >> 5;
    int x = v;
    #pragma unroll
    for (int o = 1; o < 32; o <<= 1) {
        int y = __shfl_up_sync(0xFFFFFFFFu, x, o);
        if (lane >= o) x += y;
    }
    if (lane == 31) ws[warp] = x;
    __syncthreads();
    if (warp == 0) {               // scan warp sums (inclusive)
        int w = ws[lane];
        #pragma unroll
        for (int o = 1; o < 32; o <<= 1) {
            int y = __shfl_up_sync(0xFFFFFFFFu, w, o);
            if (lane >= o) w += y;
        }
        ws[lane] = w;
        if (lane == 31) {          // publish block total
            __threadfence();
            atomicExch(&g_bsum[bid], w + 1);
        }
    }
    __syncthreads();
    if (warp == 1) {               // spin for all block totals, scan them
        int s = 0;
        if (lane < SCAN_BLOCKS) {
            do { s = atomicAdd(&g_bsum[lane], 0); } while (s == 0);
            s -= 1;
        }
        int b = s;
        #pragma unroll
        for (int o = 1; o < 32; o <<= 1) {
            int y = __shfl_up_sync(0xFFFFFFFFu, s, o);
            if (lane >= o) s += y;
        }
        boff[lane] = s - b;        // exclusive block prefix
        if (bid == 0 && lane == SCAN_BLOCKS - 1) g_off[N_NODES] = s;
    }
    __syncthreads();
    int excl = x - v + ((warp > 0) ? ws[warp - 1] : 0) + boff[bid];
    if (i < N_NODES) { g_off[i] = excl; g_cur[i] = excl; }
}

__global__ void k_fill(const int* __restrict__ ei) {
    int t = blockIdx.x * blockDim.x + threadIdx.x;
    if (t < EDGE_Q) {
        #pragma unroll
        for (int i = 0; i < 4; i++) {
            int e = t + i * EDGE_Q;
            int s = ei[e];
            int d = ei[N_EDGES + e];
            int pos = atomicAdd(&g_cur[d], 1);
            g_col[pos] = s;
        }
    }
}

// ---------------- GIN aggregation (bf16 in, fp32 acc, bf16 out) ----------
__global__ void k_agg(const float* __restrict__ eps, int layer) {
    int gt = blockIdx.x * blockDim.x + threadIdx.x;
    int node = gt >> 5;
    if (node >= N_NODES) return;
    int lane = gt & 31;
    float epsv = 1.0f + eps[layer];
    const uint2* hb = (const uint2*)g_hb;
    uint2 sv = hb[(size_t)node * 32 + lane];
    float4 acc;
    acc.x = bflo(sv.x) * epsv; acc.y = bfhi(sv.x) * epsv;
    acc.z = bflo(sv.y) * epsv; acc.w = bfhi(sv.y) * epsv;
    int e = g_off[node], end = g_off[node + 1];
    for (; e + 3 < end; e += 4) {
        int c0 = g_col[e], c1 = g_col[e + 1], c2 = g_col[e + 2], c3 = g_col[e + 3];
        uint2 v0 = hb[(size_t)c0 * 32 + lane];
        uint2 v1 = hb[(size_t)c1 * 32 + lane];
        uint2 v2 = hb[(size_t)c2 * 32 + lane];
        uint2 v3 = hb[(size_t)c3 * 32 + lane];
        acc.x += (bflo(v0.x) + bflo(v1.x)) + (bflo(v2.x) + bflo(v3.x));
        acc.y += (bfhi(v0.x) + bfhi(v1.x)) + (bfhi(v2.x) + bfhi(v3.x));
        acc.z += (bflo(v0.y) + bflo(v1.y)) + (bflo(v2.y) + bflo(v3.y));
        acc.w += (bfhi(v0.y) + bfhi(v1.y)) + (bfhi(v2.y) + bfhi(v3.y));
    }
    for (; e < end; e++) {
        int c = g_col[e];
        uint2 v = hb[(size_t)c * 32 + lane];
        acc.x += bflo(v.x); acc.y += bfhi(v.x);
        acc.z += bflo(v.y); acc.w += bfhi(v.y);
    }
    uint2 o;
    o.x = bfpack(acc.x, acc.y);
    o.y = bfpack(acc.z, acc.w);
    ((uint2*)g_aggb)[(size_t)node * 32 + lane] = o;
}

// ---------------- fused layer via mma.sync (HMMA bf16, f32 acc) ----------
// TILE 192 x 128, 384 threads (12 warps), warp tile 32x64. Grid 131 = 1 wave.
#define FM 192
#define APITCHB 272                 // bytes per A/W row (136 bf16)
#define OFF_W1H 52224               // 192*272
#define OFF_W1L (OFF_W1H + 34816)   // 128*272
#define OFF_W2H (OFF_W1L + 34816)
#define OFF_W2L (OFF_W2H + 34816)
#define OFF_CONS (OFF_W2L + 34816)  // 191488
#define FUSED_SMEM (OFF_CONS + 1536)

__device__ __forceinline__ void gemm_tile(
    uint32_t aB0, uint32_t aB1, uint32_t wHiB, uint32_t wLoB, float acc[2][8][4])
{
    #pragma unroll
    for (int k0 = 0; k0 < 128; k0 += 16) {
        uint a0[4], a1[4];
        ldsm4(a0, aB0 + k0 * 2);
        ldsm4(a1, aB1 + k0 * 2);
        #pragma unroll
        for (int np = 0; np < 4; np++) {
            uint b[4];
            ldsm4t(b, wHiB + k0 * APITCHB + np * 32);
            mma16816(acc[0][2*np],     a0, b);
            mma16816(acc[0][2*np + 1], a0, b + 2);
            mma16816(acc[1][2*np],     a1, b);
            mma16816(acc[1][2*np + 1], a1, b + 2);
            ldsm4t(b, wLoB + k0 * APITCHB + np * 32);
            mma16816(acc[0][2*np],     a0, b);
            mma16816(acc[0][2*np + 1], a0, b + 2);
            mma16816(acc[1][2*np],     a1, b);
            mma16816(acc[1][2*np + 1], a1, b + 2);
        }
    }
}

template <int LAST>
__global__ void __launch_bounds__(384, 1) k_fused(
    int layer, int M,
    const float* __restrict__ b1, const float* __restrict__ gamma,
    const float* __restrict__ beta, const float* __restrict__ mean,
    const float* __restrict__ var, const float* __restrict__ b2)
{
    extern __shared__ char sm[];
    float* cons = (float*)(sm + OFF_CONS);
    int tid = threadIdx.x;
    int m0 = blockIdx.x * FM;
    uint32_t sb = smem_u32(sm);

    // ---- weights via cp.async: group0 = W1 hi+lo, group1 = W2 hi+lo ----
    {
        const char* w1h = (const char*)g_whi[layer][0];
        const char* w1l = (const char*)g_wlo[layer][0];
        const char* w2h = (const char*)g_whi[layer][1];
        const char* w2l = (const char*)g_wlo[layer][1];
        for (int i = tid; i < 2176; i += 384) {
            cpa16(sb + OFF_W1H + i * 16, w1h + i * 16);
            cpa16(sb + OFF_W1L + i * 16, w1l + i * 16);
        }
        CPA_COMMIT();
        for (int i = tid; i < 2176; i += 384) {
            cpa16(sb + OFF_W2H + i * 16, w2h + i * 16);
            cpa16(sb + OFF_W2L + i * 16, w2l + i * 16);
        }
        CPA_COMMIT();
    }
    // ---- A tile: bf16 from g_aggb, 16B chunks, padded pitch ----
    {
        #pragma unroll
        for (int i = 0; i < 8; i++) {
            int idx = tid + i * 384;          // 0..3071
            int r = idx >> 4, c16 = idx & 15;
            int row = m0 + r;
            uint4 v = (row < M) ? *(const uint4*)(g_aggb + (size_t)row * 64 + c16 * 4)
                                : make_uint4(0, 0, 0, 0);
            *(uint4*)(sm + r * APITCHB + c16 * 16) = v;
        }
        if (tid < 128) {
            float s = gamma[tid] * rsqrtf(var[tid] + 1e-5f);
            cons[tid]       = s;
            cons[128 + tid] = (b1[tid] - mean[tid]) * s + beta[tid];
            cons[256 + tid] = b2[tid];
        }
    }
    CPA_WAIT(1);           // W1 hi/lo landed
    __syncthreads();

    int warp = tid >> 5;
    int lane = tid & 31;
    int mBase = (warp % 6) * 32;
    int nBase = (warp / 6) * 64;
    int lr  = lane & 15;
    int lc8 = (lane >> 4) << 3;
    int g = lane >> 2, t = lane & 3;

    uint32_t aB0 = sb + (mBase + lr) * APITCHB + lc8 * 2;
    uint32_t aB1 = aB0 + 16 * APITCHB;
    uint32_t wRow = lr * APITCHB + (nBase + lc8) * 2;

    float acc[2][8][4];
    #pragma unroll
    for (int mt = 0; mt < 2; mt++)
        #pragma unroll
        for (int ng = 0; ng < 8; ng++)
            #pragma unroll
            for (int i = 0; i < 4; i++) acc[mt][ng][i] = 0.f;

    // ---- GEMM1 ----
    gemm_tile(aB0, aB1, sb + OFF_W1H + wRow, sb + OFF_W1L + wRow, acc);

    // ---- BN + ReLU -> z overwrites A ----
    CPA_WAIT(0);           // W2 hi/lo landed
    __syncthreads();       // all A reads complete
    #pragma unroll
    for (int mt = 0; mt < 2; mt++) {
        int r0 = mBase + mt * 16 + g;
        #pragma unroll
        for (int ng = 0; ng < 8; ng++) {
            int colL = nBase + ng * 8 + 2 * t;
            float s0 = cons[colL], s1 = cons[colL + 1];
            float t0 = cons[128 + colL], t1 = cons[128 + colL + 1];
            float z00 = fmaxf(fmaf(acc[mt][ng][0], s0, t0), 0.f);
            float z01 = fmaxf(fmaf(acc[mt][ng][1], s1, t1), 0.f);
            float z10 = fmaxf(fmaf(acc[mt][ng][2], s0, t0), 0.f);
            float z11 = fmaxf(fmaf(acc[mt][ng][3], s1, t1), 0.f);
            *(uint*)(sm + r0 * APITCHB + colL * 2)       = bfpack(z00, z01);
            *(uint*)(sm + (r0 + 8) * APITCHB + colL * 2) = bfpack(z10, z11);
        }
    }
    __syncthreads();

    // ---- GEMM2 ----
    #pragma unroll
    for (int mt = 0; mt < 2; mt++)
        #pragma unroll
        for (int ng = 0; ng < 8; ng++)
            #pragma unroll
            for (int i = 0; i < 4; i++) acc[mt][ng][i] = 0.f;
    gemm_tile(aB0, aB1, sb + OFF_W2H + wRow, sb + OFF_W2L + wRow, acc);

    // ---- bias + ReLU -> output ----
    #pragma unroll
    for (int mt = 0; mt < 2; mt++) {
        int r0 = m0 + mBase + mt * 16 + g;
        #pragma unroll
        for (int ng = 0; ng < 8; ng++) {
            int colL = nBase + ng * 8 + 2 * t;
            float bb0 = cons[256 + colL], bb1 = cons[256 + colL + 1];
            float o00 = fmaxf(acc[mt][ng][0] + bb0, 0.f);
            float o01 = fmaxf(acc[mt][ng][1] + bb1, 0.f);
            float o10 = fmaxf(acc[mt][ng][2] + bb0, 0.f);
            float o11 = fmaxf(acc[mt][ng][3] + bb1, 0.f);
            if (LAST) {
                if (r0 < M)     *(float2*)(g_h + (size_t)r0 * D + colL)       = make_float2(o00, o01);
                if (r0 + 8 < M) *(float2*)(g_h + (size_t)(r0 + 8) * D + colL) = make_float2(o10, o11);
            } else {
                if (r0 < M)     g_hb[(size_t)r0 * 64 + colL / 2]       = bfpack(o00, o01);
                if (r0 + 8 < M) g_hb[(size_t)(r0 + 8) * 64 + colL / 2] = bfpack(o10, o11);
            }
        }
    }
}

// ---------------- mean-pool per graph + final linear + state re-zero -------
__global__ void k_pool(const float* __restrict__ h, const int* __restrict__ batch,
                       const float* __restrict__ Wout, const float* __restrict__ bout,
                       float* __restrict__ out)
{
    int g = blockIdx.x;
    int t = threadIdx.x;   // 128

    // re-zero CSR state for the NEXT launch (g_deg / g_bsum)
    int gt = g * 128 + t;            // 0..65535 covers N_NODES
    if (gt < N_NODES) g_deg[gt] = 0;
    if (gt < 32) g_bsum[gt] = 0;

    int lo = 0, hi = N_NODES;
    while (lo < hi) { int mid = (lo + hi) >> 1; if (batch[mid] < g) lo = mid + 1; else hi = mid; }
    int start = lo;
    lo = start; hi = N_NODES;
    while (lo < hi) { int mid = (lo + hi) >> 1; if (batch[mid] < g + 1) lo = mid + 1; else hi = mid; }
    int stop = lo;

    float s = 0.f;
    for (int n = start; n < stop; n++) s += h[(size_t)n * D + t];
    float cnt = fmaxf((float)(stop - start), 1.f);

    __shared__ float sp[D];
    sp[t] = s / cnt;
    __syncthreads();

    if (t < D_OUT) {
        float acc = bout[t];
        #pragma unroll 8
        for (int k = 0; k < D; k++) acc += sp[k] * Wout[k * D_OUT + t];
        out[g * D_OUT + t] = acc;
    }
}

// ---------------- host launcher ----------------
extern "C" void kernel_launch(void* const* d_in, const int* in_sizes, int n_in,
                              void* d_out, int out_size)
{
    const float* x     = (const float*)d_in[0];
    const int*   ei    = (const int*)d_in[1];
    const int*   batch = (const int*)d_in[2];
    const float* W1    = (const float*)d_in[3];
    const float* b1    = (const float*)d_in[4];
    const float* gamma = (const float*)d_in[5];
    const float* beta  = (const float*)d_in[6];
    const float* rmean = (const float*)d_in[7];
    const float* rvar  = (const float*)d_in[8];
    const float* W2    = (const float*)d_in[9];
    const float* b2    = (const float*)d_in[10];
    const float* eps   = (const float*)d_in[11];
    const float* Wout  = (const float*)d_in[12];
    const float* bout  = (const float*)d_in[13];
    float* out = (float*)d_out;

    float* p_h;
    cudaGetSymbolAddress((void**)&p_h, g_h);

    cudaFuncSetAttribute(k_fused<0>, cudaFuncAttributeMaxDynamicSharedMemorySize, FUSED_SMEM);
    cudaFuncSetAttribute(k_fused<1>, cudaFuncAttributeMaxDynamicSharedMemorySize, FUSED_SMEM);

    // ---- prep (+hist) + CSR build (deterministic every call) ----
    k_prep<<<(N_NODES * D / 8 + 255) / 256, 256>>>(x, W1, W2, ei);
    k_scan<<<SCAN_BLOCKS, 1024>>>();
    k_fill<<<(EDGE_Q + 255) / 256, 256>>>(ei);

    const int fused_blocks = (N_NODES + FM - 1) / FM;    // 131
    const int agg_blocks   = (N_NODES * 32 + 255) / 256;

    for (int l = 0; l < N_LAYERS; l++) {
        k_agg<<<agg_blocks, 256>>>(eps, l);
        if (l < N_LAYERS - 1) {
            k_fused<0><<<fused_blocks, 384, FUSED_SMEM>>>(
                l, N_NODES, b1 + l * D, gamma + l * D, beta + l * D,
                rmean + l * D, rvar + l * D, b2 + l * D);
        } else {
            k_fused<1><<<fused_blocks, 384, FUSED_SMEM>>>(
                l, N_NODES, b1 + l * D, gamma + l * D, beta + l * D,
                rmean + l * D, rvar + l * D, b2 + l * D);
        }
    }

    k_pool<<<N_GRAPHS, D>>>(p_h, batch, Wout, bout, out);
}

// round 16
// speedup vs baseline: 1.4468x; 1.0133x over previous
#include <cuda_runtime.h>
#include <cstdint>

#define N_NODES 25000
#define N_EDGES 400000
#define D       128
#define N_LAYERS 3
#define N_GRAPHS 512
#define D_OUT   10

typedef unsigned int uint;

// ---------------- device scratch ----------------
// NOTE: g_deg and g_bsum are zero at module load AND re-zeroed by k_pool at
// the END of every launch, so every kernel_launch execution (correctness run,
// capture replays) starts from the same zeroed state. Deterministic.
__device__ float    g_h[N_NODES * D];            // fp32 h3 (pool input)
__device__ unsigned g_hb[N_NODES * D / 2];       // bf16x2 h (agg input)
__device__ unsigned g_aggb[N_NODES * D / 2];     // bf16x2 agg (GEMM1 A input)
__device__ unsigned g_whi[N_LAYERS][2][128 * 68]; // bf16x2 W hi, padded pitch 136
__device__ unsigned g_wlo[N_LAYERS][2][128 * 68]; // bf16x2 W lo
__device__ int      g_deg[N_NODES];
__device__ int      g_off[N_NODES + 1];
__device__ int      g_cur[N_NODES];
__device__ int      g_col[N_EDGES];
__device__ int      g_bsum[32];

// ---------------- helpers ----------
__device__ __forceinline__ unsigned bfpack(float e0, float e1) {
    unsigned r;   // low half = bf16(e0), high half = bf16(e1)
    asm("cvt.rn.bf16x2.f32 %0, %1, %2;" : "=r"(r) : "f"(e1), "f"(e0));
    return r;
}
__device__ __forceinline__ float bflo(unsigned p) { return __uint_as_float(p << 16); }
__device__ __forceinline__ float bfhi(unsigned p) { return __uint_as_float(p & 0xFFFF0000u); }

__device__ __forceinline__ uint32_t smem_u32(const void* p) {
    uint32_t a;
    asm("{ .reg .u64 t; cvta.to.shared.u64 t, %1; cvt.u32.u64 %0, t; }" : "=r"(a) : "l"(p));
    return a;
}
__device__ __forceinline__ void cpa16(uint32_t dst, const void* src) {
    asm volatile("cp.async.cg.shared.global [%0], [%1], 16;" :: "r"(dst), "l"(src));
}
#define CPA_COMMIT() asm volatile("cp.async.commit_group;" ::: "memory")
#define CPA_WAIT(n)  asm volatile("cp.async.wait_group %0;" :: "n"(n) : "memory")

__device__ __forceinline__ void ldsm4(uint* r, uint32_t addr) {
    asm volatile("ldmatrix.sync.aligned.m8n8.x4.shared.b16 {%0,%1,%2,%3}, [%4];"
                 : "=r"(r[0]), "=r"(r[1]), "=r"(r[2]), "=r"(r[3]) : "r"(addr));
}
__device__ __forceinline__ void ldsm4t(uint* r, uint32_t addr) {
    asm volatile("ldmatrix.sync.aligned.m8n8.x4.trans.shared.b16 {%0,%1,%2,%3}, [%4];"
                 : "=r"(r[0]), "=r"(r[1]), "=r"(r[2]), "=r"(r[3]) : "r"(addr));
}
__device__ __forceinline__ void mma16816(float* c, const uint* a, const uint* b) {
    asm volatile(
        "mma.sync.aligned.m16n8k16.row.col.f32.bf16.bf16.f32 "
        "{%0,%1,%2,%3}, {%4,%5,%6,%7}, {%8,%9}, {%0,%1,%2,%3};"
        : "+f"(c[0]), "+f"(c[1]), "+f"(c[2]), "+f"(c[3])
        : "r"(a[0]), "r"(a[1]), "r"(a[2]), "r"(a[3]), "r"(b[0]), "r"(b[1]));
}

// ---------------- prep: x->bf16, W->hi/lo split, degree histogram ----------
#define EDGE_Q (N_EDGES / 4)

__global__ void k_prep(const float* __restrict__ x, const float* __restrict__ W1,
                       const float* __restrict__ W2, const int* __restrict__ ei) {
    int t = blockIdx.x * blockDim.x + threadIdx.x;
    if (t < N_NODES * D / 8) {             // 400000: x -> bf16
        float4 v0 = *(const float4*)(x + t * 8);
        float4 v1 = *(const float4*)(x + t * 8 + 4);
        uint4 o;
        o.x = bfpack(v0.x, v0.y);
        o.y = bfpack(v0.z, v0.w);
        o.z = bfpack(v1.x, v1.y);
        o.w = bfpack(v1.z, v1.w);
        *(uint4*)(g_hb + t * 4) = o;
    }
    if (t < 3 * 2 * 128 * 64) {            // 49152: weight hi/lo split
        int e2 = t & 63;
        int r  = (t >> 6) & 127;
        int m  = t >> 13;
        int l = m >> 1, j = m & 1;
        const float* src = (j ? W2 : W1) + (size_t)l * 16384 + r * 128 + e2 * 2;
        float v0 = src[0], v1 = src[1];
        unsigned hi = bfpack(v0, v1);
        unsigned lo = bfpack(v0 - bflo(hi), v1 - bfhi(hi));
        int idx = r * 68 + e2;
        g_whi[l][j][idx] = hi;
        g_wlo[l][j][idx] = lo;
    }
    if (t < EDGE_Q) {                      // 100000: degree histogram (4 edges)
        int d0 = ei[N_EDGES + t];
        int d1 = ei[N_EDGES + t + EDGE_Q];
        int d2 = ei[N_EDGES + t + 2 * EDGE_Q];
        int d3 = ei[N_EDGES + t + 3 * EDGE_Q];
        atomicAdd(&g_deg[d0], 1);
        atomicAdd(&g_deg[d1], 1);
        atomicAdd(&g_deg[d2], 1);
        atomicAdd(&g_deg[d3], 1);
    }
}

// ---------------- single-kernel scan with inter-block spin lookback --------
#define SCAN_BLOCKS 25

__global__ void k_scan() {
    __shared__ int ws[32];
    __shared__ int boff[32];
    int bid = blockIdx.x;
    int i = bid * 1024 + threadIdx.x;
    int v = (i < N_NODES) ? g_deg[i] : 0;
    int lane = threadIdx.x & 31, warp = threadIdx.x >> 5;
    int x = v;
    #pragma unroll
    for (int o = 1; o < 32; o <<= 1) {
        int y = __shfl_up_sync(0xFFFFFFFFu, x, o);
        if (lane >= o) x += y;
    }
    if (lane == 31) ws[warp] = x;
    __syncthreads();
    if (warp == 0) {               // scan warp sums (inclusive)
        int w = ws[lane];
        #pragma unroll
        for (int o = 1; o < 32; o <<= 1) {
            int y = __shfl_up_sync(0xFFFFFFFFu, w, o);
            if (lane >= o) w += y;
        }
        ws[lane] = w;
        if (lane == 31) {          // publish block total
            __threadfence();
            atomicExch(&g_bsum[bid], w + 1);
        }
    }
    __syncthreads();
    if (warp == 1) {               // spin for all block totals, scan them
        int s = 0;
        if (lane < SCAN_BLOCKS) {
            do { s = atomicAdd(&g_bsum[lane], 0); } while (s == 0);
            s -= 1;
        }
        int b = s;
        #pragma unroll
        for (int o = 1; o < 32; o <<= 1) {
            int y = __shfl_up_sync(0xFFFFFFFFu, s, o);
            if (lane >= o) s += y;
        }
        boff[lane] = s - b;        // exclusive block prefix
        if (bid == 0 && lane == SCAN_BLOCKS - 1) g_off[N_NODES] = s;
    }
    __syncthreads();
    int excl = x - v + ((warp > 0) ? ws[warp - 1] : 0) + boff[bid];
    if (i < N_NODES) { g_off[i] = excl; g_cur[i] = excl; }
}

__global__ void k_fill(const int* __restrict__ ei) {
    int t = blockIdx.x * blockDim.x + threadIdx.x;
    if (t < EDGE_Q) {
        #pragma unroll
        for (int i = 0; i < 4; i++) {
            int e = t + i * EDGE_Q;
            int s = ei[e];
            int d = ei[N_EDGES + e];
            int pos = atomicAdd(&g_cur[d], 1);
            g_col[pos] = s;
        }
    }
}

// ---------------- GIN aggregation (bf16 in, fp32 acc, bf16 out) ----------
// one warp per node; 8-deep edge unroll (MLP=8 to cover L2 latency)
__global__ void k_agg(const float* __restrict__ eps, int layer) {
    int gt = blockIdx.x * blockDim.x + threadIdx.x;
    int node = gt >> 5;
    if (node >= N_NODES) return;
    int lane = gt & 31;
    float epsv = 1.0f + eps[layer];
    const uint2* hb = (const uint2*)g_hb;
    uint2 sv = hb[(size_t)node * 32 + lane];
    float4 acc;
    acc.x = bflo(sv.x) * epsv; acc.y = bfhi(sv.x) * epsv;
    acc.z = bflo(sv.y) * epsv; acc.w = bfhi(sv.y) * epsv;
    int e = g_off[node], end = g_off[node + 1];
    for (; e + 7 < end; e += 8) {
        int c0 = g_col[e],     c1 = g_col[e + 1];
        int c2 = g_col[e + 2], c3 = g_col[e + 3];
        int c4 = g_col[e + 4], c5 = g_col[e + 5];
        int c6 = g_col[e + 6], c7 = g_col[e + 7];
        uint2 v0 = hb[(size_t)c0 * 32 + lane];
        uint2 v1 = hb[(size_t)c1 * 32 + lane];
        uint2 v2 = hb[(size_t)c2 * 32 + lane];
        uint2 v3 = hb[(size_t)c3 * 32 + lane];
        uint2 v4 = hb[(size_t)c4 * 32 + lane];
        uint2 v5 = hb[(size_t)c5 * 32 + lane];
        uint2 v6 = hb[(size_t)c6 * 32 + lane];
        uint2 v7 = hb[(size_t)c7 * 32 + lane];
        acc.x += ((bflo(v0.x) + bflo(v1.x)) + (bflo(v2.x) + bflo(v3.x)))
               + ((bflo(v4.x) + bflo(v5.x)) + (bflo(v6.x) + bflo(v7.x)));
        acc.y += ((bfhi(v0.x) + bfhi(v1.x)) + (bfhi(v2.x) + bfhi(v3.x)))
               + ((bfhi(v4.x) + bfhi(v5.x)) + (bfhi(v6.x) + bfhi(v7.x)));
        acc.z += ((bflo(v0.y) + bflo(v1.y)) + (bflo(v2.y) + bflo(v3.y)))
               + ((bflo(v4.y) + bflo(v5.y)) + (bflo(v6.y) + bflo(v7.y)));
        acc.w += ((bfhi(v0.y) + bfhi(v1.y)) + (bfhi(v2.y) + bfhi(v3.y)))
               + ((bfhi(v4.y) + bfhi(v5.y)) + (bfhi(v6.y) + bfhi(v7.y)));
    }
    for (; e + 3 < end; e += 4) {
        int c0 = g_col[e], c1 = g_col[e + 1], c2 = g_col[e + 2], c3 = g_col[e + 3];
        uint2 v0 = hb[(size_t)c0 * 32 + lane];
        uint2 v1 = hb[(size_t)c1 * 32 + lane];
        uint2 v2 = hb[(size_t)c2 * 32 + lane];
        uint2 v3 = hb[(size_t)c3 * 32 + lane];
        acc.x += (bflo(v0.x) + bflo(v1.x)) + (bflo(v2.x) + bflo(v3.x));
        acc.y += (bfhi(v0.x) + bfhi(v1.x)) + (bfhi(v2.x) + bfhi(v3.x));
        acc.z += (bflo(v0.y) + bflo(v1.y)) + (bflo(v2.y) + bflo(v3.y));
        acc.w += (bfhi(v0.y) + bfhi(v1.y)) + (bfhi(v2.y) + bfhi(v3.y));
    }
    for (; e < end; e++) {
        int c = g_col[e];
        uint2 v = hb[(size_t)c * 32 + lane];
        acc.x += bflo(v.x); acc.y += bfhi(v.x);
        acc.z += bflo(v.y); acc.w += bfhi(v.y);
    }
    uint2 o;
    o.x = bfpack(acc.x, acc.y);
    o.y = bfpack(acc.z, acc.w);
    ((uint2*)g_aggb)[(size_t)node * 32 + lane] = o;
}

// ---------------- fused layer via mma.sync (HMMA bf16, f32 acc) ----------
// TILE 192 x 128, 384 threads (12 warps), warp tile 32x64. Grid 131 = 1 wave.
#define FM 192
#define APITCHB 272                 // bytes per A/W row (136 bf16)
#define OFF_W1H 52224               // 192*272
#define OFF_W1L (OFF_W1H + 34816)   // 128*272
#define OFF_W2H (OFF_W1L + 34816)
#define OFF_W2L (OFF_W2H + 34816)
#define OFF_CONS (OFF_W2L + 34816)  // 191488
#define FUSED_SMEM (OFF_CONS + 1536)

__device__ __forceinline__ void gemm_tile(
    uint32_t aB0, uint32_t aB1, uint32_t wHiB, uint32_t wLoB, float acc[2][8][4])
{
    #pragma unroll
    for (int k0 = 0; k0 < 128; k0 += 16) {
        uint a0[4], a1[4];
        ldsm4(a0, aB0 + k0 * 2);
        ldsm4(a1, aB1 + k0 * 2);
        #pragma unroll
        for (int np = 0; np < 4; np++) {
            uint b[4];
            ldsm4t(b, wHiB + k0 * APITCHB + np * 32);
            mma16816(acc[0][2*np],     a0, b);
            mma16816(acc[0][2*np + 1], a0, b + 2);
            mma16816(acc[1][2*np],     a1, b);
            mma16816(acc[1][2*np + 1], a1, b + 2);
            ldsm4t(b, wLoB + k0 * APITCHB + np * 32);
            mma16816(acc[0][2*np],     a0, b);
            mma16816(acc[0][2*np + 1], a0, b + 2);
            mma16816(acc[1][2*np],     a1, b);
            mma16816(acc[1][2*np + 1], a1, b + 2);
        }
    }
}

template <int LAST>
__global__ void __launch_bounds__(384, 1) k_fused(
    int layer, int M,
    const float* __restrict__ b1, const float* __restrict__ gamma,
    const float* __restrict__ beta, const float* __restrict__ mean,
    const float* __restrict__ var, const float* __restrict__ b2)
{
    extern __shared__ char sm[];
    float* cons = (float*)(sm + OFF_CONS);
    int tid = threadIdx.x;
    int m0 = blockIdx.x * FM;
    uint32_t sb = smem_u32(sm);

    // ---- W1 hi+lo via cp.async (group 0) ----
    {
        const char* w1h = (const char*)g_whi[layer][0];
        const char* w1l = (const char*)g_wlo[layer][0];
        for (int i = tid; i < 2176; i += 384) {
            cpa16(sb + OFF_W1H + i * 16, w1h + i * 16);
            cpa16(sb + OFF_W1L + i * 16, w1l + i * 16);
        }
        CPA_COMMIT();
    }
    // ---- A tile LDGs issued EARLY (latency overlaps W2 issue + cons) ----
    {
        #pragma unroll
        for (int i = 0; i < 8; i++) {
            int idx = tid + i * 384;          // 0..3071
            int r = idx >> 4, c16 = idx & 15;
            int row = m0 + r;
            uint4 v = (row < M) ? *(const uint4*)(g_aggb + (size_t)row * 64 + c16 * 4)
                                : make_uint4(0, 0, 0, 0);
            *(uint4*)(sm + r * APITCHB + c16 * 16) = v;
        }
    }
    // ---- W2 hi+lo via cp.async (group 1) ----
    {
        const char* w2h = (const char*)g_whi[layer][1];
        const char* w2l = (const char*)g_wlo[layer][1];
        for (int i = tid; i < 2176; i += 384) {
            cpa16(sb + OFF_W2H + i * 16, w2h + i * 16);
            cpa16(sb + OFF_W2L + i * 16, w2l + i * 16);
        }
        CPA_COMMIT();
        if (tid < 128) {
            float s = gamma[tid] * rsqrtf(var[tid] + 1e-5f);
            cons[tid]       = s;
            cons[128 + tid] = (b1[tid] - mean[tid]) * s + beta[tid];
            cons[256 + tid] = b2[tid];
        }
    }
    CPA_WAIT(1);           // W1 hi/lo landed (W2 may be in flight)
    __syncthreads();

    int warp = tid >> 5;
    int lane = tid & 31;
    int mBase = (warp % 6) * 32;
    int nBase = (warp / 6) * 64;
    int lr  = lane & 15;
    int lc8 = (lane >> 4) << 3;
    int g = lane >> 2, t = lane & 3;

    uint32_t aB0 = sb + (mBase + lr) * APITCHB + lc8 * 2;
    uint32_t aB1 = aB0 + 16 * APITCHB;
    uint32_t wRow = lr * APITCHB + (nBase + lc8) * 2;

    float acc[2][8][4];
    #pragma unroll
    for (int mt = 0; mt < 2; mt++)
        #pragma unroll
        for (int ng = 0; ng < 8; ng++)
            #pragma unroll
            for (int i = 0; i < 4; i++) acc[mt][ng][i] = 0.f;

    // ---- GEMM1 ----
    gemm_tile(aB0, aB1, sb + OFF_W1H + wRow, sb + OFF_W1L + wRow, acc);

    // ---- BN + ReLU -> z overwrites A ----
    CPA_WAIT(0);           // W2 hi/lo landed
    __syncthreads();       // all A reads complete
    #pragma unroll
    for (int mt = 0; mt < 2; mt++) {
        int r0 = mBase + mt * 16 + g;
        #pragma unroll
        for (int ng = 0; ng < 8; ng++) {
            int colL = nBase + ng * 8 + 2 * t;
            float s0 = cons[colL], s1 = cons[colL + 1];
            float t0 = cons[128 + colL], t1 = cons[128 + colL + 1];
            float z00 = fmaxf(fmaf(acc[mt][ng][0], s0, t0), 0.f);
            float z01 = fmaxf(fmaf(acc[mt][ng][1], s1, t1), 0.f);
            float z10 = fmaxf(fmaf(acc[mt][ng][2], s0, t0), 0.f);
            float z11 = fmaxf(fmaf(acc[mt][ng][3], s1, t1), 0.f);
            *(uint*)(sm + r0 * APITCHB + colL * 2)       = bfpack(z00, z01);
            *(uint*)(sm + (r0 + 8) * APITCHB + colL * 2) = bfpack(z10, z11);
        }
    }
    __syncthreads();

    // ---- GEMM2 ----
    #pragma unroll
    for (int mt = 0; mt < 2; mt++)
        #pragma unroll
        for (int ng = 0; ng < 8; ng++)
            #pragma unroll
            for (int i = 0; i < 4; i++) acc[mt][ng][i] = 0.f;
    gemm_tile(aB0, aB1, sb + OFF_W2H + wRow, sb + OFF_W2L + wRow, acc);

    // ---- bias + ReLU -> output ----
    #pragma unroll
    for (int mt = 0; mt < 2; mt++) {
        int r0 = m0 + mBase + mt * 16 + g;
        #pragma unroll
        for (int ng = 0; ng < 8; ng++) {
            int colL = nBase + ng * 8 + 2 * t;
            float bb0 = cons[256 + colL], bb1 = cons[256 + colL + 1];
            float o00 = fmaxf(acc[mt][ng][0] + bb0, 0.f);
            float o01 = fmaxf(acc[mt][ng][1] + bb1, 0.f);
            float o10 = fmaxf(acc[mt][ng][2] + bb0, 0.f);
            float o11 = fmaxf(acc[mt][ng][3] + bb1, 0.f);
            if (LAST) {
                if (r0 < M)     *(float2*)(g_h + (size_t)r0 * D + colL)       = make_float2(o00, o01);
                if (r0 + 8 < M) *(float2*)(g_h + (size_t)(r0 + 8) * D + colL) = make_float2(o10, o11);
            } else {
                if (r0 < M)     g_hb[(size_t)r0 * 64 + colL / 2]       = bfpack(o00, o01);
                if (r0 + 8 < M) g_hb[(size_t)(r0 + 8) * 64 + colL / 2] = bfpack(o10, o11);
            }
        }
    }
}

// ---------------- mean-pool per graph + final linear + state re-zero -------
__global__ void k_pool(const float* __restrict__ h, const int* __restrict__ batch,
                       const float* __restrict__ Wout, const float* __restrict__ bout,
                       float* __restrict__ out)
{
    int g = blockIdx.x;
    int t = threadIdx.x;   // 128

    // re-zero CSR state for the NEXT launch (g_deg / g_bsum)
    int gt = g * 128 + t;            // 0..65535 covers N_NODES
    if (gt < N_NODES) g_deg[gt] = 0;
    if (gt < 32) g_bsum[gt] = 0;

    int lo = 0, hi = N_NODES;
    while (lo < hi) { int mid = (lo + hi) >> 1; if (batch[mid] < g) lo = mid + 1; else hi = mid; }
    int start = lo;
    lo = start; hi = N_NODES;
    while (lo < hi) { int mid = (lo + hi) >> 1; if (batch[mid] < g + 1) lo = mid + 1; else hi = mid; }
    int stop = lo;

    float s = 0.f;
    for (int n = start; n < stop; n++) s += h[(size_t)n * D + t];
    float cnt = fmaxf((float)(stop - start), 1.f);

    __shared__ float sp[D];
    sp[t] = s / cnt;
    __syncthreads();

    if (t < D_OUT) {
        float acc = bout[t];
        #pragma unroll 8
        for (int k = 0; k < D; k++) acc += sp[k] * Wout[k * D_OUT + t];
        out[g * D_OUT + t] = acc;
    }
}

// ---------------- host launcher ----------------
extern "C" void kernel_launch(void* const* d_in, const int* in_sizes, int n_in,
                              void* d_out, int out_size)
{
    const float* x     = (const float*)d_in[0];
    const int*   ei    = (const int*)d_in[1];
    const int*   batch = (const int*)d_in[2];
    const float* W1    = (const float*)d_in[3];
    const float* b1    = (const float*)d_in[4];
    const float* gamma = (const float*)d_in[5];
    const float* beta  = (const float*)d_in[6];
    const float* rmean = (const float*)d_in[7];
    const float* rvar  = (const float*)d_in[8];
    const float* W2    = (const float*)d_in[9];
    const float* b2    = (const float*)d_in[10];
    const float* eps   = (const float*)d_in[11];
    const float* Wout  = (const float*)d_in[12];
    const float* bout  = (const float*)d_in[13];
    float* out = (float*)d_out;

    float* p_h;
    cudaGetSymbolAddress((void**)&p_h, g_h);

    cudaFuncSetAttribute(k_fused<0>, cudaFuncAttributeMaxDynamicSharedMemorySize, FUSED_SMEM);
    cudaFuncSetAttribute(k_fused<1>, cudaFuncAttributeMaxDynamicSharedMemorySize, FUSED_SMEM);

    // ---- prep (+hist) + CSR build (deterministic every call) ----
    k_prep<<<(N_NODES * D / 8 + 255) / 256, 256>>>(x, W1, W2, ei);
    k_scan<<<SCAN_BLOCKS, 1024>>>();
    k_fill<<<(EDGE_Q + 255) / 256, 256>>>(ei);

    const int fused_blocks = (N_NODES + FM - 1) / FM;    // 131
    const int agg_blocks   = (N_NODES * 32 + 255) / 256;

    for (int l = 0; l < N_LAYERS; l++) {
        k_agg<<<agg_blocks, 256>>>(eps, l);
        if (l < N_LAYERS - 1) {
            k_fused<0><<<fused_blocks, 384, FUSED_SMEM>>>(
                l, N_NODES, b1 + l * D, gamma + l * D, beta + l * D,
                rmean + l * D, rvar + l * D, b2 + l * D);
        } else {
            k_fused<1><<<fused_blocks, 384, FUSED_SMEM>>>(
                l, N_NODES, b1 + l * D, gamma + l * D, beta + l * D,
                rmean + l * D, rvar + l * D, b2 + l * D);
        }
    }

    k_pool<<<N_GRAPHS, D>>>(p_h, batch, Wout, bout, out);
}